// round 14
// baseline (speedup 1.0000x reference)
#include <cuda_runtime.h>
#include <math.h>
#include <stdint.h>

// Problem constants
#define Bc  2
#define Sc  2048
#define Dc  1024
#define Hc  16
#define HDc 64
#define BSc (Bc * Sc)
#define BHS (Bc * Hc * Sc)   // 65536 attention rows
#define ATTN_ELEMS_C ((size_t)Bc * Hc * Sc * Sc)   // 134,217,728

// Scratch (device globals; allocation inside kernel_launch is forbidden)
__device__ float g_q[(size_t)Bc * Sc * Dc];
__device__ float g_k[(size_t)Bc * Sc * Dc];
__device__ float g_v[(size_t)Bc * Sc * Dc];
__device__ float g_ctx[(size_t)Bc * Sc * Dc];
__device__ float g_mbuf[BHS];
__device__ float g_lbuf[BHS];
__device__ float g_attn_scratch[ATTN_ELEMS_C];
// RN-tf32 pre-rounded operands (so cp.async + HW truncation is EXACT)
__device__ float g_inq[(size_t)BSc * Dc];
__device__ float g_ink[(size_t)BSc * Dc];
__device__ float g_inv[(size_t)BSc * Dc];
__device__ float g_wq[(size_t)Dc * Dc];
__device__ float g_wk[(size_t)Dc * Dc];
__device__ float g_wv[(size_t)Dc * Dc];
__device__ float g_wo[(size_t)Dc * Dc];

// ---------------------------------------------------------------------------
// tf32 helpers. cvt.rna rounds-to-nearest into a tf32-representable fp32
// pattern; mma operands below that pattern are truncated EXACTLY.
// ---------------------------------------------------------------------------
__device__ __forceinline__ uint32_t f2tf(float f) {
    uint32_t u;
    asm("cvt.rna.tf32.f32 %0, %1;" : "=r"(u) : "f"(f));
    return u;
}
__device__ __forceinline__ float frnd(float f) { return __uint_as_float(f2tf(f)); }
__device__ __forceinline__ uint32_t fbits(float f) { return __float_as_uint(f); }

__device__ __forceinline__ void mma8(float c[4],
                                     uint32_t a0, uint32_t a1, uint32_t a2, uint32_t a3,
                                     uint32_t b0, uint32_t b1) {
    asm volatile(
        "mma.sync.aligned.m16n8k8.row.col.f32.tf32.tf32.f32 "
        "{%0,%1,%2,%3}, {%4,%5,%6,%7}, {%8,%9}, {%0,%1,%2,%3};"
        : "+f"(c[0]), "+f"(c[1]), "+f"(c[2]), "+f"(c[3])
        : "r"(a0), "r"(a1), "r"(a2), "r"(a3), "r"(b0), "r"(b1));
}

// cp.async helpers (16B, L1-bypass)
__device__ __forceinline__ void cpa16(uint32_t s, const void* g) {
    asm volatile("cp.async.cg.shared.global [%0], [%1], 16;" :: "r"(s), "l"(g));
}
#define CPA_COMMIT() asm volatile("cp.async.commit_group;")
#define CPA_WAIT0()  asm volatile("cp.async.wait_group 0;")

// ---------------------------------------------------------------------------
// Pre-round: RN-tf32 copies of inputs and weights.
// ---------------------------------------------------------------------------
__global__ __launch_bounds__(256) void pre_round(
    const float* __restrict__ q_in, const float* __restrict__ k_in,
    const float* __restrict__ v_in,
    const float* __restrict__ Wq, const float* __restrict__ Wk,
    const float* __restrict__ Wv, const float* __restrict__ Wo) {
    const float* src;
    float* dst;
    size_t n;   // float4 count
    switch (blockIdx.y) {
        case 0: src = q_in; dst = g_inq; n = (size_t)BSc * Dc / 4; break;
        case 1: src = k_in; dst = g_ink; n = (size_t)BSc * Dc / 4; break;
        case 2: src = v_in; dst = g_inv; n = (size_t)BSc * Dc / 4; break;
        case 3: src = Wq;   dst = g_wq;  n = (size_t)Dc * Dc / 4;  break;
        case 4: src = Wk;   dst = g_wk;  n = (size_t)Dc * Dc / 4;  break;
        case 5: src = Wv;   dst = g_wv;  n = (size_t)Dc * Dc / 4;  break;
        default: src = Wo;  dst = g_wo;  n = (size_t)Dc * Dc / 4;  break;
    }
    size_t i = (size_t)blockIdx.x * 256 + threadIdx.x;
    if (i >= n) return;
    float4 v = *((const float4*)src + i);
    v.x = frnd(v.x); v.y = frnd(v.y); v.z = frnd(v.z); v.w = frnd(v.w);
    *((float4*)dst + i) = v;
}

// ---------------------------------------------------------------------------
// TF32 GEMM + bias, cp.async 2-stage double buffer. Operands MUST be
// pre-rounded to tf32. C[M,N] = A[M,K] @ W[K,N] + b[N].
// CTA 128x128, BK=32, 256 thr, warp 64x32.
// ---------------------------------------------------------------------------
#define GA_W   (128 * 36)
#define GB_W   (32 * 132)
#define GST_W  (GA_W + GB_W)                  // 8832 words / stage
#define GEMM_SMEM_BYTES (2 * GST_W * 4)       // 70656 B

__device__ __forceinline__ void gemm_stage(uint32_t sA, uint32_t sB,
                                           const float* __restrict__ A,
                                           const float* __restrict__ W,
                                           int N, int K, int m0, int n0, int k0,
                                           int tid) {
#pragma unroll
    for (int i = 0; i < 4; i++) {
        int idx = tid + i * 256;
        int r = idx >> 3, c4 = idx & 7;
        cpa16(sA + (uint32_t)(r * 36 + c4 * 4) * 4,
              &A[(size_t)(m0 + r) * K + k0 + c4 * 4]);
    }
#pragma unroll
    for (int i = 0; i < 4; i++) {
        int idx = tid + i * 256;
        int r = idx >> 5, c4 = idx & 31;
        cpa16(sB + (uint32_t)(r * 132 + c4 * 4) * 4,
              &W[(size_t)(k0 + r) * N + n0 + c4 * 4]);
    }
}

__device__ __forceinline__ void gemm_body(const float* __restrict__ A,
                                          const float* __restrict__ W,
                                          const float* __restrict__ bias,
                                          float* __restrict__ C,
                                          int M, int N, int K,
                                          uint32_t* sh, bool round_out) {
    const int tid = threadIdx.x;
    const int w = tid >> 5, lane = tid & 31;
    const int g = lane >> 2, t = lane & 3;
    const int m0 = blockIdx.x * 128, n0 = blockIdx.y * 128;
    const int wm = (w & 1) * 64;
    const int wn = (w >> 1) * 32;

    const uint32_t smem_u32 = (uint32_t)__cvta_generic_to_shared(sh);

    float acc[4][4][4] = {};

    gemm_stage(smem_u32, smem_u32 + GA_W * 4, A, W, N, K, m0, n0, 0, tid);
    CPA_COMMIT();

    const int NIT = K / 32;
    for (int i = 0; i < NIT; i++) {
        CPA_WAIT0();
        __syncthreads();   // stage i visible; prior MMA reads done

        const int nb = (i + 1) & 1;
        if (i + 1 < NIT) {
            gemm_stage(smem_u32 + (uint32_t)(nb * GST_W) * 4,
                       smem_u32 + (uint32_t)(nb * GST_W + GA_W) * 4,
                       A, W, N, K, m0, n0, (i + 1) * 32, tid);
            CPA_COMMIT();
        }

        const uint32_t* As = sh + (i & 1) * GST_W;
        const uint32_t* Bs = As + GA_W;

#pragma unroll
        for (int ks = 0; ks < 4; ks++) {
            uint32_t a[4][4], bb[4][2];
#pragma unroll
            for (int mf = 0; mf < 4; mf++) {
                int r = wm + mf * 16 + g;
                a[mf][0] = As[r * 36 + ks * 8 + t];
                a[mf][2] = As[r * 36 + ks * 8 + t + 4];
                a[mf][1] = As[(r + 8) * 36 + ks * 8 + t];
                a[mf][3] = As[(r + 8) * 36 + ks * 8 + t + 4];
            }
#pragma unroll
            for (int nf = 0; nf < 4; nf++) {
                bb[nf][0] = Bs[(ks * 8 + t) * 132 + wn + nf * 8 + g];
                bb[nf][1] = Bs[(ks * 8 + t + 4) * 132 + wn + nf * 8 + g];
            }
#pragma unroll
            for (int mf = 0; mf < 4; mf++)
#pragma unroll
                for (int nf = 0; nf < 4; nf++)
                    mma8(acc[mf][nf], a[mf][0], a[mf][1], a[mf][2], a[mf][3],
                         bb[nf][0], bb[nf][1]);
        }
        __syncthreads();   // MMA reads of buffer i&1 done before re-stage
    }

#pragma unroll
    for (int mf = 0; mf < 4; mf++) {
#pragma unroll
        for (int nf = 0; nf < 4; nf++) {
            int col = n0 + wn + nf * 8 + 2 * t;
            float b0v = bias[col], b1v = bias[col + 1];
            int row = m0 + wm + mf * 16 + g;
            float2 v0 = {acc[mf][nf][0] + b0v, acc[mf][nf][1] + b1v};
            float2 v1 = {acc[mf][nf][2] + b0v, acc[mf][nf][3] + b1v};
            if (round_out) {   // downstream kernel uses these as MMA operands
                v0.x = frnd(v0.x); v0.y = frnd(v0.y);
                v1.x = frnd(v1.x); v1.y = frnd(v1.y);
            }
            *(float2*)&C[(size_t)row * N + col] = v0;
            *(float2*)&C[(size_t)(row + 8) * N + col] = v1;
        }
    }
}

// Fused QKV projection: blockIdx.z selects (input, weights, bias, output).
__global__ __launch_bounds__(256) void qkv_gemm(
    const float* __restrict__ bq, const float* __restrict__ bk,
    const float* __restrict__ bv) {
    extern __shared__ uint32_t sh[];
    const float *A, *W, *bias;
    float* C;
    if (blockIdx.z == 0)      { A = g_inq; W = g_wq; bias = bq; C = g_q; }
    else if (blockIdx.z == 1) { A = g_ink; W = g_wk; bias = bk; C = g_k; }
    else                      { A = g_inv; W = g_wv; bias = bv; C = g_v; }
    gemm_body(A, W, bias, C, BSc, Dc, Dc, sh, true);
}

// ---------------------------------------------------------------------------
// Fused tail: output-projection GEMM (z==0, 256 CTAs) co-scheduled with the
// grid-stride attn normalization (z>=1, 1280 CTAs). Both depend only on
// attn_flash; the tensor-bound GEMM hides under the DRAM-bound normalize.
// ---------------------------------------------------------------------------
#define NORM_BLOCKS 1280

__global__ __launch_bounds__(256) void fused_tail(const float* __restrict__ bo,
                                                  float* __restrict__ out,
                                                  float* __restrict__ attn) {
    if (blockIdx.z == 0) {
        extern __shared__ uint32_t sh[];
        gemm_body(g_ctx, g_wo, bo, out, BSc, Dc, Dc, sh, false);
        return;
    }
    // Normalize: attn[i] = exp(raw - m_row) / l_row, streaming in place
    const size_t total = ATTN_ELEMS_C / 4;           // float4 count
    const size_t nb = (size_t)(blockIdx.z - 1) * 256 + blockIdx.y * 32 + blockIdx.x;
    const size_t stride = (size_t)NORM_BLOCKS * 256;
    for (size_t i4 = nb * 256 + threadIdx.x; i4 < total; i4 += stride) {
        int row = (int)(i4 >> 9);                    // 512 float4 per row
        float mm = g_mbuf[row];
        float il = 1.0f / g_lbuf[row];
        float4 v = __ldcs((const float4*)attn + i4);
        v.x = __expf(v.x - mm) * il;
        v.y = __expf(v.y - mm) * il;
        v.z = __expf(v.z - mm) * il;
        v.w = __expf(v.w - mm) * il;
        __stcs((float4*)attn + i4, v);
    }
}

// ---------------------------------------------------------------------------
// Flash attention: 128-query CTA, warp-private softmax (16q x 64k per warp).
// Q/K/V are already tf32-rounded -> raw-bit staging is exact. P gets cvt.rna.
// m/l in registers; 2 syncthreads + 1 syncwarp per slab; K/V reg prefetch.
// Smem words: Qs 128*68 | Ks 64*68 | Vs 64*72 | Ps 8*1088  = 26368 (105472 B)
// ---------------------------------------------------------------------------
#define AQ    0
#define AK    8704
#define AV    13056
#define APT   17664
#define AWORDS 26368
#define ATTN_SMEM_BYTES (AWORDS * 4)

__global__ __launch_bounds__(256, 2) void attn_flash(float* __restrict__ attn) {
    extern __shared__ uint32_t sh[];
    uint32_t* Qs = sh + AQ;          // Q bits [q][d] stride 68 (pre-scaled)
    uint32_t* Ks = sh + AK;          // K bits [key][d] stride 68
    uint32_t* Vs = sh + AV;          // V bits [key][d] stride 72
    uint32_t* Ps = sh + APT;         // per-warp P bits [16][64] stride 68

    const int tid = threadIdx.x;
    const int w = tid >> 5, lane = tid & 31;
    const int g = lane >> 2, t = lane & 3;
    const int b = blockIdx.z, h = blockIdx.y, q0 = blockIdx.x << 7;
    const int wq = w * 16;

    const int row_g = (b * Hc + h) * Sc + q0;
    float* attn_base = attn + (size_t)row_g * Sc;
    const float* kbase = g_k + ((size_t)b * Sc) * Dc + h * HDc;
    const float* vbase = g_v + ((size_t)b * Sc) * Dc + h * HDc;

    const int r0 = tid >> 4, c4 = tid & 15;
    uint32_t* Pw = Ps + w * 1088;

    // Stage Q 128x64 (x 0.125, exact power of two -> stays tf32)
#pragma unroll
    for (int i = 0; i < 8; i++) {
        int idx = tid + i * 256;
        int r = idx >> 4, cc = idx & 15;
        float4 v = *(const float4*)&g_q[((size_t)b * Sc + q0 + r) * Dc + h * HDc + cc * 4];
        uint32_t* p = &Qs[r * 68 + cc * 4];
        p[0] = fbits(v.x * 0.125f); p[1] = fbits(v.y * 0.125f);
        p[2] = fbits(v.z * 0.125f); p[3] = fbits(v.w * 0.125f);
    }

    // Prefetch + stage slab 0 (raw bits, already tf32)
    float4 kv[4], vv[4];
#pragma unroll
    for (int i = 0; i < 4; i++) {
        int r = r0 + 16 * i;
        kv[i] = *(const float4*)&kbase[(size_t)r * Dc + c4 * 4];
        vv[i] = *(const float4*)&vbase[(size_t)r * Dc + c4 * 4];
    }
#pragma unroll
    for (int i = 0; i < 4; i++) {
        int r = r0 + 16 * i;
        *(uint4*)&Ks[r * 68 + c4 * 4] = *(uint4*)&kv[i];
        *(uint4*)&Vs[r * 72 + c4 * 4] = *(uint4*)&vv[i];
    }

    float m0r = -INFINITY, m1r = -INFINITY;
    float l0r = 0.0f, l1r = 0.0f;
    float acc[8][4] = {};

    for (int s = 0; s < 32; s++) {
        __syncthreads();   // staged K/V visible

        if (s + 1 < 32) {
            const int kk = (s + 1) << 6;
#pragma unroll
            for (int i = 0; i < 4; i++)
                kv[i] = *(const float4*)&kbase[(size_t)(kk + r0 + 16 * i) * Dc + c4 * 4];
        }

        // ---- Score MMA: 16q x 64k per warp ----
        float c[8][4] = {};
#pragma unroll
        for (int ks = 0; ks < 8; ks++) {
            uint32_t a0 = Qs[(wq + g) * 68 + ks * 8 + t];
            uint32_t a1 = Qs[(wq + g + 8) * 68 + ks * 8 + t];
            uint32_t a2 = Qs[(wq + g) * 68 + ks * 8 + t + 4];
            uint32_t a3 = Qs[(wq + g + 8) * 68 + ks * 8 + t + 4];
#pragma unroll
            for (int nf = 0; nf < 8; nf++) {
                uint32_t b0 = Ks[(nf * 8 + g) * 68 + ks * 8 + t];
                uint32_t b1 = Ks[(nf * 8 + g) * 68 + ks * 8 + t + 4];
                mma8(c[nf], a0, a1, a2, a3, b0, b1);
            }
        }

        if (s + 1 < 32) {
            const int kk = (s + 1) << 6;
#pragma unroll
            for (int i = 0; i < 4; i++)
                vv[i] = *(const float4*)&vbase[(size_t)(kk + r0 + 16 * i) * Dc + c4 * 4];
        }

        // ---- Raw score STG (streaming, evict-first) + row max ----
        float mx0 = -INFINITY, mx1 = -INFINITY;
#pragma unroll
        for (int nf = 0; nf < 8; nf++) {
            int col = (s << 6) + nf * 8 + 2 * t;
            __stcs((float2*)&attn_base[(size_t)(wq + g) * Sc + col],
                   make_float2(c[nf][0], c[nf][1]));
            __stcs((float2*)&attn_base[(size_t)(wq + g + 8) * Sc + col],
                   make_float2(c[nf][2], c[nf][3]));
            mx0 = fmaxf(mx0, fmaxf(c[nf][0], c[nf][1]));
            mx1 = fmaxf(mx1, fmaxf(c[nf][2], c[nf][3]));
        }
#pragma unroll
        for (int d = 1; d < 4; d <<= 1) {
            mx0 = fmaxf(mx0, __shfl_xor_sync(0xffffffffu, mx0, d));
            mx1 = fmaxf(mx1, __shfl_xor_sync(0xffffffffu, mx1, d));
        }
        const float mn0 = fmaxf(m0r, mx0), mn1 = fmaxf(m1r, mx1);
        const float f0 = __expf(m0r - mn0), f1 = __expf(m1r - mn1);
        m0r = mn0; m1r = mn1;

        // ---- exp in regs, P store (cvt.rna — fp32-born operand), l update ----
        float s0 = 0.0f, s1 = 0.0f;
#pragma unroll
        for (int nf = 0; nf < 8; nf++) {
            float p0 = __expf(c[nf][0] - mn0);
            float p1 = __expf(c[nf][1] - mn0);
            float p2 = __expf(c[nf][2] - mn1);
            float p3 = __expf(c[nf][3] - mn1);
            s0 += p0 + p1; s1 += p2 + p3;
            uint2 w0 = {f2tf(p0), f2tf(p1)};
            *(uint2*)&Pw[g * 68 + nf * 8 + 2 * t] = w0;
            uint2 w1 = {f2tf(p2), f2tf(p3)};
            *(uint2*)&Pw[(g + 8) * 68 + nf * 8 + 2 * t] = w1;
        }
#pragma unroll
        for (int d = 1; d < 4; d <<= 1) {
            s0 += __shfl_xor_sync(0xffffffffu, s0, d);
            s1 += __shfl_xor_sync(0xffffffffu, s1, d);
        }
        l0r = l0r * f0 + s0;
        l1r = l1r * f1 + s1;
        __syncwarp();

        // ---- Rescale acc + PV MMA ----
#pragma unroll
        for (int nf = 0; nf < 8; nf++) {
            acc[nf][0] *= f0; acc[nf][1] *= f0;
            acc[nf][2] *= f1; acc[nf][3] *= f1;
        }
#pragma unroll
        for (int ks = 0; ks < 8; ks++) {
            const int kb = ks * 8;
            uint32_t a0 = Pw[g * 68 + kb + t];
            uint32_t a1 = Pw[(g + 8) * 68 + kb + t];
            uint32_t a2 = Pw[g * 68 + kb + t + 4];
            uint32_t a3 = Pw[(g + 8) * 68 + kb + t + 4];
#pragma unroll
            for (int nf = 0; nf < 8; nf++) {
                uint32_t b0 = Vs[(kb + t) * 72 + nf * 8 + g];
                uint32_t b1 = Vs[(kb + t + 4) * 72 + nf * 8 + g];
                mma8(acc[nf], a0, a1, a2, a3, b0, b1);
            }
        }
        __syncthreads();

        if (s + 1 < 32) {
#pragma unroll
            for (int i = 0; i < 4; i++) {
                int r = r0 + 16 * i;
                *(uint4*)&Ks[r * 68 + c4 * 4] = *(uint4*)&kv[i];
                *(uint4*)&Vs[r * 72 + c4 * 4] = *(uint4*)&vv[i];
            }
        }
    }

    if (t == 0) {
        g_mbuf[row_g + wq + g] = m0r;
        g_lbuf[row_g + wq + g] = l0r;
        g_mbuf[row_g + wq + g + 8] = m1r;
        g_lbuf[row_g + wq + g + 8] = l1r;
    }

    // Context epilogue: out = acc / l, RN-rounded to tf32 (feeds out projection)
    const float il0 = 1.0f / l0r, il1 = 1.0f / l1r;
#pragma unroll
    for (int nf = 0; nf < 8; nf++) {
        int col = nf * 8 + 2 * t;
        *(float2*)&g_ctx[((size_t)b * Sc + q0 + wq + g) * Dc + h * HDc + col] =
            make_float2(frnd(acc[nf][0] * il0), frnd(acc[nf][1] * il0));
        *(float2*)&g_ctx[((size_t)b * Sc + q0 + wq + g + 8) * Dc + h * HDc + col] =
            make_float2(frnd(acc[nf][2] * il1), frnd(acc[nf][3] * il1));
    }
}

// ---------------------------------------------------------------------------
extern "C" void kernel_launch(void* const* d_in, const int* in_sizes, int n_in,
                              void* d_out, int out_size) {
    const float* query = (const float*)d_in[0];
    const float* key_  = (const float*)d_in[1];
    const float* value = (const float*)d_in[2];
    const float* Wq = (const float*)d_in[3];
    const float* bq = (const float*)d_in[4];
    const float* Wk = (const float*)d_in[5];
    const float* bk = (const float*)d_in[6];
    const float* Wv = (const float*)d_in[7];
    const float* bv = (const float*)d_in[8];
    const float* Wo = (const float*)d_in[9];
    const float* bo = (const float*)d_in[10];
    float* out = (float*)d_out;

    const size_t OUT_ELEMS = (size_t)Bc * Sc * Dc;            // 4,194,304
    float* attn_ptr;
    if ((size_t)out_size >= OUT_ELEMS + ATTN_ELEMS_C) {
        attn_ptr = out + OUT_ELEMS;
    } else {
        cudaGetSymbolAddress((void**)&attn_ptr, g_attn_scratch);
    }

    cudaFuncSetAttribute(attn_flash,
                         cudaFuncAttributeMaxDynamicSharedMemorySize,
                         ATTN_SMEM_BYTES);
    cudaFuncSetAttribute(qkv_gemm,
                         cudaFuncAttributeMaxDynamicSharedMemorySize,
                         GEMM_SMEM_BYTES);
    cudaFuncSetAttribute(fused_tail,
                         cudaFuncAttributeMaxDynamicSharedMemorySize,
                         GEMM_SMEM_BYTES);

    // RN-round inputs + weights to tf32 (makes all cp.async truncation exact)
    pre_round<<<dim3(4096, 7), 256>>>(query, key_, value, Wq, Wk, Wv, Wo);

    // Fused Q/K/V projections (outputs RN-rounded to tf32)
    qkv_gemm<<<dim3(BSc / 128, Dc / 128, 3), 256, GEMM_SMEM_BYTES>>>(bq, bk, bv);

    attn_flash<<<dim3(Sc / 128, Hc, Bc), 256, ATTN_SMEM_BYTES>>>(attn_ptr);

    // Output projection (z=0) co-scheduled with streaming normalize (z>=1)
    fused_tail<<<dim3(32, 8, 6), 256, GEMM_SMEM_BYTES>>>(bo, out, attn_ptr);
}

// round 15
// speedup vs baseline: 1.1588x; 1.1588x over previous
#include <cuda_runtime.h>
#include <math.h>
#include <stdint.h>

// Problem constants
#define Bc  2
#define Sc  2048
#define Dc  1024
#define Hc  16
#define HDc 64
#define BSc (Bc * Sc)
#define BHS (Bc * Hc * Sc)   // 65536 attention rows
#define ATTN_ELEMS_C ((size_t)Bc * Hc * Sc * Sc)   // 134,217,728

// Scratch (device globals; allocation inside kernel_launch is forbidden)
__device__ float g_q[(size_t)Bc * Sc * Dc];
__device__ float g_k[(size_t)Bc * Sc * Dc];
__device__ float g_v[(size_t)Bc * Sc * Dc];
__device__ float g_ctx[(size_t)Bc * Sc * Dc];
__device__ float g_mbuf[BHS];
__device__ float g_lbuf[BHS];
__device__ float g_attn_scratch[ATTN_ELEMS_C];
// RN-tf32 pre-rounded operands (so cp.async + HW truncation is EXACT)
__device__ float g_inq[(size_t)BSc * Dc];
__device__ float g_ink[(size_t)BSc * Dc];
__device__ float g_inv[(size_t)BSc * Dc];
__device__ float g_wq[(size_t)Dc * Dc];
__device__ float g_wk[(size_t)Dc * Dc];
__device__ float g_wv[(size_t)Dc * Dc];
__device__ float g_wo[(size_t)Dc * Dc];

// ---------------------------------------------------------------------------
// tf32 helpers. cvt.rna rounds-to-nearest into a tf32-representable fp32
// pattern; mma operands below that pattern are truncated EXACTLY.
// ---------------------------------------------------------------------------
__device__ __forceinline__ uint32_t f2tf(float f) {
    uint32_t u;
    asm("cvt.rna.tf32.f32 %0, %1;" : "=r"(u) : "f"(f));
    return u;
}
__device__ __forceinline__ float frnd(float f) { return __uint_as_float(f2tf(f)); }
__device__ __forceinline__ uint32_t fbits(float f) { return __float_as_uint(f); }

__device__ __forceinline__ void mma8(float c[4],
                                     uint32_t a0, uint32_t a1, uint32_t a2, uint32_t a3,
                                     uint32_t b0, uint32_t b1) {
    asm volatile(
        "mma.sync.aligned.m16n8k8.row.col.f32.tf32.tf32.f32 "
        "{%0,%1,%2,%3}, {%4,%5,%6,%7}, {%8,%9}, {%0,%1,%2,%3};"
        : "+f"(c[0]), "+f"(c[1]), "+f"(c[2]), "+f"(c[3])
        : "r"(a0), "r"(a1), "r"(a2), "r"(a3), "r"(b0), "r"(b1));
}

// cp.async helpers (16B, L1-bypass)
__device__ __forceinline__ void cpa16(uint32_t s, const void* g) {
    asm volatile("cp.async.cg.shared.global [%0], [%1], 16;" :: "r"(s), "l"(g));
}
#define CPA_COMMIT() asm volatile("cp.async.commit_group;")
#define CPA_WAIT0()  asm volatile("cp.async.wait_group 0;")

// ---------------------------------------------------------------------------
// Pre-round: RN-tf32 copies of inputs and weights.
// ---------------------------------------------------------------------------
__global__ __launch_bounds__(256) void pre_round(
    const float* __restrict__ q_in, const float* __restrict__ k_in,
    const float* __restrict__ v_in,
    const float* __restrict__ Wq, const float* __restrict__ Wk,
    const float* __restrict__ Wv, const float* __restrict__ Wo) {
    const float* src;
    float* dst;
    size_t n;   // float4 count
    switch (blockIdx.y) {
        case 0: src = q_in; dst = g_inq; n = (size_t)BSc * Dc / 4; break;
        case 1: src = k_in; dst = g_ink; n = (size_t)BSc * Dc / 4; break;
        case 2: src = v_in; dst = g_inv; n = (size_t)BSc * Dc / 4; break;
        case 3: src = Wq;   dst = g_wq;  n = (size_t)Dc * Dc / 4;  break;
        case 4: src = Wk;   dst = g_wk;  n = (size_t)Dc * Dc / 4;  break;
        case 5: src = Wv;   dst = g_wv;  n = (size_t)Dc * Dc / 4;  break;
        default: src = Wo;  dst = g_wo;  n = (size_t)Dc * Dc / 4;  break;
    }
    size_t i = (size_t)blockIdx.x * 256 + threadIdx.x;
    if (i >= n) return;
    float4 v = *((const float4*)src + i);
    v.x = frnd(v.x); v.y = frnd(v.y); v.z = frnd(v.z); v.w = frnd(v.w);
    *((float4*)dst + i) = v;
}

// ---------------------------------------------------------------------------
// TF32 GEMM + bias, cp.async 2-stage double buffer (128x128 tile version,
// used for the QKV projections). Operands MUST be pre-rounded to tf32.
// ---------------------------------------------------------------------------
#define GA_W   (128 * 36)
#define GB_W   (32 * 132)
#define GST_W  (GA_W + GB_W)                  // 8832 words / stage
#define GEMM_SMEM_BYTES (2 * GST_W * 4)       // 70656 B

__device__ __forceinline__ void gemm_stage(uint32_t sA, uint32_t sB,
                                           const float* __restrict__ A,
                                           const float* __restrict__ W,
                                           int N, int K, int m0, int n0, int k0,
                                           int tid) {
#pragma unroll
    for (int i = 0; i < 4; i++) {
        int idx = tid + i * 256;
        int r = idx >> 3, c4 = idx & 7;
        cpa16(sA + (uint32_t)(r * 36 + c4 * 4) * 4,
              &A[(size_t)(m0 + r) * K + k0 + c4 * 4]);
    }
#pragma unroll
    for (int i = 0; i < 4; i++) {
        int idx = tid + i * 256;
        int r = idx >> 5, c4 = idx & 31;
        cpa16(sB + (uint32_t)(r * 132 + c4 * 4) * 4,
              &W[(size_t)(k0 + r) * N + n0 + c4 * 4]);
    }
}

__device__ __forceinline__ void gemm_body(const float* __restrict__ A,
                                          const float* __restrict__ W,
                                          const float* __restrict__ bias,
                                          float* __restrict__ C,
                                          int M, int N, int K,
                                          uint32_t* sh, bool round_out) {
    const int tid = threadIdx.x;
    const int w = tid >> 5, lane = tid & 31;
    const int g = lane >> 2, t = lane & 3;
    const int m0 = blockIdx.x * 128, n0 = blockIdx.y * 128;
    const int wm = (w & 1) * 64;
    const int wn = (w >> 1) * 32;

    const uint32_t smem_u32 = (uint32_t)__cvta_generic_to_shared(sh);

    float acc[4][4][4] = {};

    gemm_stage(smem_u32, smem_u32 + GA_W * 4, A, W, N, K, m0, n0, 0, tid);
    CPA_COMMIT();

    const int NIT = K / 32;
    for (int i = 0; i < NIT; i++) {
        CPA_WAIT0();
        __syncthreads();   // stage i visible; prior MMA reads done

        const int nb = (i + 1) & 1;
        if (i + 1 < NIT) {
            gemm_stage(smem_u32 + (uint32_t)(nb * GST_W) * 4,
                       smem_u32 + (uint32_t)(nb * GST_W + GA_W) * 4,
                       A, W, N, K, m0, n0, (i + 1) * 32, tid);
            CPA_COMMIT();
        }

        const uint32_t* As = sh + (i & 1) * GST_W;
        const uint32_t* Bs = As + GA_W;

#pragma unroll
        for (int ks = 0; ks < 4; ks++) {
            uint32_t a[4][4], bb[4][2];
#pragma unroll
            for (int mf = 0; mf < 4; mf++) {
                int r = wm + mf * 16 + g;
                a[mf][0] = As[r * 36 + ks * 8 + t];
                a[mf][2] = As[r * 36 + ks * 8 + t + 4];
                a[mf][1] = As[(r + 8) * 36 + ks * 8 + t];
                a[mf][3] = As[(r + 8) * 36 + ks * 8 + t + 4];
            }
#pragma unroll
            for (int nf = 0; nf < 4; nf++) {
                bb[nf][0] = Bs[(ks * 8 + t) * 132 + wn + nf * 8 + g];
                bb[nf][1] = Bs[(ks * 8 + t + 4) * 132 + wn + nf * 8 + g];
            }
#pragma unroll
            for (int mf = 0; mf < 4; mf++)
#pragma unroll
                for (int nf = 0; nf < 4; nf++)
                    mma8(acc[mf][nf], a[mf][0], a[mf][1], a[mf][2], a[mf][3],
                         bb[nf][0], bb[nf][1]);
        }
        __syncthreads();   // MMA reads of buffer i&1 done before re-stage
    }

#pragma unroll
    for (int mf = 0; mf < 4; mf++) {
#pragma unroll
        for (int nf = 0; nf < 4; nf++) {
            int col = n0 + wn + nf * 8 + 2 * t;
            float b0v = bias[col], b1v = bias[col + 1];
            int row = m0 + wm + mf * 16 + g;
            float2 v0 = {acc[mf][nf][0] + b0v, acc[mf][nf][1] + b1v};
            float2 v1 = {acc[mf][nf][2] + b0v, acc[mf][nf][3] + b1v};
            if (round_out) {   // downstream kernel uses these as MMA operands
                v0.x = frnd(v0.x); v0.y = frnd(v0.y);
                v1.x = frnd(v1.x); v1.y = frnd(v1.y);
            }
            *(float2*)&C[(size_t)row * N + col] = v0;
            *(float2*)&C[(size_t)(row + 8) * N + col] = v1;
        }
    }
}

// Fused QKV projection: blockIdx.z selects (input, weights, bias, output).
__global__ __launch_bounds__(256) void qkv_gemm(
    const float* __restrict__ bq, const float* __restrict__ bk,
    const float* __restrict__ bv) {
    extern __shared__ uint32_t sh[];
    const float *A, *W, *bias;
    float* C;
    if (blockIdx.z == 0)      { A = g_inq; W = g_wq; bias = bq; C = g_q; }
    else if (blockIdx.z == 1) { A = g_ink; W = g_wk; bias = bk; C = g_k; }
    else                      { A = g_inv; W = g_wv; bias = bv; C = g_v; }
    gemm_body(A, W, bias, C, BSc, Dc, Dc, sh, true);
}

// ---------------------------------------------------------------------------
// Fused tail v2 — occupancy-safe.
// z = 0..7  : grid-stride streaming normalize (2048 CTAs, launched FIRST)
// z = 8..11 : output-projection GEMM, 64x64 tiles (1024 CTAs, backfill)
// Small smem (35840 B) + __launch_bounds__(256,4) keep 4 CTAs/SM for the
// DRAM-bound normalize while the tensor-bound GEMM hides under it.
// ---------------------------------------------------------------------------
#define SGA_W  (64 * 36)                       // 2304 words
#define SGB_W  (32 * 68)                       // 2176 words
#define SGST_W (SGA_W + SGB_W)                 // 4480 words / stage
#define TAIL_SMEM_BYTES (2 * SGST_W * 4)       // 35840 B
#define NORM_CTAS 2048

__global__ __launch_bounds__(256, 4) void fused_tail(const float* __restrict__ bo,
                                                     float* __restrict__ out,
                                                     float* __restrict__ attn) {
    if (blockIdx.z < 8) {
        // ---- Streaming normalize: attn[i] = exp(raw - m_row) / l_row ----
        const size_t total = ATTN_ELEMS_C / 4;       // float4 count
        const size_t nb = (size_t)blockIdx.z * 256 + blockIdx.y * 32 + blockIdx.x;
        const size_t stride = (size_t)NORM_CTAS * 256;
        for (size_t i4 = nb * 256 + threadIdx.x; i4 < total; i4 += stride) {
            int row = (int)(i4 >> 9);                // 512 float4 per row
            float mm = g_mbuf[row];
            float il = 1.0f / g_lbuf[row];
            float4 v = __ldcs((const float4*)attn + i4);
            v.x = __expf(v.x - mm) * il;
            v.y = __expf(v.y - mm) * il;
            v.z = __expf(v.z - mm) * il;
            v.w = __expf(v.w - mm) * il;
            __stcs((float4*)attn + i4, v);
        }
        return;
    }

    // ---- Output projection: out = ctx @ Wo + bo, 64x64 CTA tile ----
    extern __shared__ uint32_t sh[];
    const int tid = threadIdx.x;
    const int w = tid >> 5, lane = tid & 31;
    const int g = lane >> 2, t = lane & 3;

    const int tile_id = (blockIdx.z - 8) * 256 + blockIdx.y * 32 + blockIdx.x;
    const int m0 = (tile_id & 63) * 64;          // 64 M-tiles
    const int n0 = (tile_id >> 6) * 64;          // 16 N-tiles
    const int wm = (w & 1) * 32;
    const int wn = (w >> 1) * 16;

    const float* A = g_ctx;
    const float* W = g_wo;
    const uint32_t smem_u32 = (uint32_t)__cvta_generic_to_shared(sh);

    float acc[2][2][4] = {};

    // Stage k0 into buffer 0
#pragma unroll
    for (int i = 0; i < 2; i++) {
        int idx = tid + i * 256;
        int r = idx >> 3, c4 = idx & 7;
        cpa16(smem_u32 + (uint32_t)(r * 36 + c4 * 4) * 4,
              &A[(size_t)(m0 + r) * Dc + c4 * 4]);
    }
#pragma unroll
    for (int i = 0; i < 2; i++) {
        int idx = tid + i * 256;
        int r = idx >> 4, c4 = idx & 15;
        cpa16(smem_u32 + (uint32_t)(SGA_W + r * 68 + c4 * 4) * 4,
              &W[(size_t)r * Dc + n0 + c4 * 4]);
    }
    CPA_COMMIT();

    const int NIT = Dc / 32;
    for (int i = 0; i < NIT; i++) {
        CPA_WAIT0();
        __syncthreads();

        const int nb = (i + 1) & 1;
        if (i + 1 < NIT) {
            const int k0 = (i + 1) * 32;
            uint32_t sA = smem_u32 + (uint32_t)(nb * SGST_W) * 4;
            uint32_t sB = smem_u32 + (uint32_t)(nb * SGST_W + SGA_W) * 4;
#pragma unroll
            for (int j = 0; j < 2; j++) {
                int idx = tid + j * 256;
                int r = idx >> 3, c4 = idx & 7;
                cpa16(sA + (uint32_t)(r * 36 + c4 * 4) * 4,
                      &A[(size_t)(m0 + r) * Dc + k0 + c4 * 4]);
            }
#pragma unroll
            for (int j = 0; j < 2; j++) {
                int idx = tid + j * 256;
                int r = idx >> 4, c4 = idx & 15;
                cpa16(sB + (uint32_t)(r * 68 + c4 * 4) * 4,
                      &W[(size_t)(k0 + r) * Dc + n0 + c4 * 4]);
            }
            CPA_COMMIT();
        }

        const uint32_t* As = sh + (i & 1) * SGST_W;
        const uint32_t* Bs = As + SGA_W;

#pragma unroll
        for (int ks = 0; ks < 4; ks++) {
            uint32_t a[2][4], bb[2][2];
#pragma unroll
            for (int mf = 0; mf < 2; mf++) {
                int r = wm + mf * 16 + g;
                a[mf][0] = As[r * 36 + ks * 8 + t];
                a[mf][2] = As[r * 36 + ks * 8 + t + 4];
                a[mf][1] = As[(r + 8) * 36 + ks * 8 + t];
                a[mf][3] = As[(r + 8) * 36 + ks * 8 + t + 4];
            }
#pragma unroll
            for (int nf = 0; nf < 2; nf++) {
                bb[nf][0] = Bs[(ks * 8 + t) * 68 + wn + nf * 8 + g];
                bb[nf][1] = Bs[(ks * 8 + t + 4) * 68 + wn + nf * 8 + g];
            }
#pragma unroll
            for (int mf = 0; mf < 2; mf++)
#pragma unroll
                for (int nf = 0; nf < 2; nf++)
                    mma8(acc[mf][nf], a[mf][0], a[mf][1], a[mf][2], a[mf][3],
                         bb[nf][0], bb[nf][1]);
        }
        __syncthreads();
    }

#pragma unroll
    for (int mf = 0; mf < 2; mf++) {
#pragma unroll
        for (int nf = 0; nf < 2; nf++) {
            int col = n0 + wn + nf * 8 + 2 * t;
            float b0v = bo[col], b1v = bo[col + 1];
            int row = m0 + wm + mf * 16 + g;
            *(float2*)&out[(size_t)row * Dc + col] =
                make_float2(acc[mf][nf][0] + b0v, acc[mf][nf][1] + b1v);
            *(float2*)&out[(size_t)(row + 8) * Dc + col] =
                make_float2(acc[mf][nf][2] + b0v, acc[mf][nf][3] + b1v);
        }
    }
}

// ---------------------------------------------------------------------------
// Flash attention: 128-query CTA, warp-private softmax (16q x 64k per warp).
// Q/K/V are already tf32-rounded -> raw-bit staging is exact. P gets cvt.rna.
// m/l in registers; 2 syncthreads + 1 syncwarp per slab; K/V reg prefetch.
// Smem words: Qs 128*68 | Ks 64*68 | Vs 64*72 | Ps 8*1088  = 26368 (105472 B)
// ---------------------------------------------------------------------------
#define AQ    0
#define AK    8704
#define AV    13056
#define APT   17664
#define AWORDS 26368
#define ATTN_SMEM_BYTES (AWORDS * 4)

__global__ __launch_bounds__(256, 2) void attn_flash(float* __restrict__ attn) {
    extern __shared__ uint32_t sh[];
    uint32_t* Qs = sh + AQ;          // Q bits [q][d] stride 68 (pre-scaled)
    uint32_t* Ks = sh + AK;          // K bits [key][d] stride 68
    uint32_t* Vs = sh + AV;          // V bits [key][d] stride 72
    uint32_t* Ps = sh + APT;         // per-warp P bits [16][64] stride 68

    const int tid = threadIdx.x;
    const int w = tid >> 5, lane = tid & 31;
    const int g = lane >> 2, t = lane & 3;
    const int b = blockIdx.z, h = blockIdx.y, q0 = blockIdx.x << 7;
    const int wq = w * 16;

    const int row_g = (b * Hc + h) * Sc + q0;
    float* attn_base = attn + (size_t)row_g * Sc;
    const float* kbase = g_k + ((size_t)b * Sc) * Dc + h * HDc;
    const float* vbase = g_v + ((size_t)b * Sc) * Dc + h * HDc;

    const int r0 = tid >> 4, c4 = tid & 15;
    uint32_t* Pw = Ps + w * 1088;

    // Stage Q 128x64 (x 0.125, exact power of two -> stays tf32)
#pragma unroll
    for (int i = 0; i < 8; i++) {
        int idx = tid + i * 256;
        int r = idx >> 4, cc = idx & 15;
        float4 v = *(const float4*)&g_q[((size_t)b * Sc + q0 + r) * Dc + h * HDc + cc * 4];
        uint32_t* p = &Qs[r * 68 + cc * 4];
        p[0] = fbits(v.x * 0.125f); p[1] = fbits(v.y * 0.125f);
        p[2] = fbits(v.z * 0.125f); p[3] = fbits(v.w * 0.125f);
    }

    // Prefetch + stage slab 0 (raw bits, already tf32)
    float4 kv[4], vv[4];
#pragma unroll
    for (int i = 0; i < 4; i++) {
        int r = r0 + 16 * i;
        kv[i] = *(const float4*)&kbase[(size_t)r * Dc + c4 * 4];
        vv[i] = *(const float4*)&vbase[(size_t)r * Dc + c4 * 4];
    }
#pragma unroll
    for (int i = 0; i < 4; i++) {
        int r = r0 + 16 * i;
        *(uint4*)&Ks[r * 68 + c4 * 4] = *(uint4*)&kv[i];
        *(uint4*)&Vs[r * 72 + c4 * 4] = *(uint4*)&vv[i];
    }

    float m0r = -INFINITY, m1r = -INFINITY;
    float l0r = 0.0f, l1r = 0.0f;
    float acc[8][4] = {};

    for (int s = 0; s < 32; s++) {
        __syncthreads();   // staged K/V visible

        if (s + 1 < 32) {
            const int kk = (s + 1) << 6;
#pragma unroll
            for (int i = 0; i < 4; i++)
                kv[i] = *(const float4*)&kbase[(size_t)(kk + r0 + 16 * i) * Dc + c4 * 4];
        }

        // ---- Score MMA: 16q x 64k per warp ----
        float c[8][4] = {};
#pragma unroll
        for (int ks = 0; ks < 8; ks++) {
            uint32_t a0 = Qs[(wq + g) * 68 + ks * 8 + t];
            uint32_t a1 = Qs[(wq + g + 8) * 68 + ks * 8 + t];
            uint32_t a2 = Qs[(wq + g) * 68 + ks * 8 + t + 4];
            uint32_t a3 = Qs[(wq + g + 8) * 68 + ks * 8 + t + 4];
#pragma unroll
            for (int nf = 0; nf < 8; nf++) {
                uint32_t b0 = Ks[(nf * 8 + g) * 68 + ks * 8 + t];
                uint32_t b1 = Ks[(nf * 8 + g) * 68 + ks * 8 + t + 4];
                mma8(c[nf], a0, a1, a2, a3, b0, b1);
            }
        }

        if (s + 1 < 32) {
            const int kk = (s + 1) << 6;
#pragma unroll
            for (int i = 0; i < 4; i++)
                vv[i] = *(const float4*)&vbase[(size_t)(kk + r0 + 16 * i) * Dc + c4 * 4];
        }

        // ---- Raw score STG (streaming, evict-first) + row max ----
        float mx0 = -INFINITY, mx1 = -INFINITY;
#pragma unroll
        for (int nf = 0; nf < 8; nf++) {
            int col = (s << 6) + nf * 8 + 2 * t;
            __stcs((float2*)&attn_base[(size_t)(wq + g) * Sc + col],
                   make_float2(c[nf][0], c[nf][1]));
            __stcs((float2*)&attn_base[(size_t)(wq + g + 8) * Sc + col],
                   make_float2(c[nf][2], c[nf][3]));
            mx0 = fmaxf(mx0, fmaxf(c[nf][0], c[nf][1]));
            mx1 = fmaxf(mx1, fmaxf(c[nf][2], c[nf][3]));
        }
#pragma unroll
        for (int d = 1; d < 4; d <<= 1) {
            mx0 = fmaxf(mx0, __shfl_xor_sync(0xffffffffu, mx0, d));
            mx1 = fmaxf(mx1, __shfl_xor_sync(0xffffffffu, mx1, d));
        }
        const float mn0 = fmaxf(m0r, mx0), mn1 = fmaxf(m1r, mx1);
        const float f0 = __expf(m0r - mn0), f1 = __expf(m1r - mn1);
        m0r = mn0; m1r = mn1;

        // ---- exp in regs, P store (cvt.rna — fp32-born operand), l update ----
        float s0 = 0.0f, s1 = 0.0f;
#pragma unroll
        for (int nf = 0; nf < 8; nf++) {
            float p0 = __expf(c[nf][0] - mn0);
            float p1 = __expf(c[nf][1] - mn0);
            float p2 = __expf(c[nf][2] - mn1);
            float p3 = __expf(c[nf][3] - mn1);
            s0 += p0 + p1; s1 += p2 + p3;
            uint2 w0 = {f2tf(p0), f2tf(p1)};
            *(uint2*)&Pw[g * 68 + nf * 8 + 2 * t] = w0;
            uint2 w1 = {f2tf(p2), f2tf(p3)};
            *(uint2*)&Pw[(g + 8) * 68 + nf * 8 + 2 * t] = w1;
        }
#pragma unroll
        for (int d = 1; d < 4; d <<= 1) {
            s0 += __shfl_xor_sync(0xffffffffu, s0, d);
            s1 += __shfl_xor_sync(0xffffffffu, s1, d);
        }
        l0r = l0r * f0 + s0;
        l1r = l1r * f1 + s1;
        __syncwarp();

        // ---- Rescale acc + PV MMA ----
#pragma unroll
        for (int nf = 0; nf < 8; nf++) {
            acc[nf][0] *= f0; acc[nf][1] *= f0;
            acc[nf][2] *= f1; acc[nf][3] *= f1;
        }
#pragma unroll
        for (int ks = 0; ks < 8; ks++) {
            const int kb = ks * 8;
            uint32_t a0 = Pw[g * 68 + kb + t];
            uint32_t a1 = Pw[(g + 8) * 68 + kb + t];
            uint32_t a2 = Pw[g * 68 + kb + t + 4];
            uint32_t a3 = Pw[(g + 8) * 68 + kb + t + 4];
#pragma unroll
            for (int nf = 0; nf < 8; nf++) {
                uint32_t b0 = Vs[(kb + t) * 72 + nf * 8 + g];
                uint32_t b1 = Vs[(kb + t + 4) * 72 + nf * 8 + g];
                mma8(acc[nf], a0, a1, a2, a3, b0, b1);
            }
        }
        __syncthreads();

        if (s + 1 < 32) {
#pragma unroll
            for (int i = 0; i < 4; i++) {
                int r = r0 + 16 * i;
                *(uint4*)&Ks[r * 68 + c4 * 4] = *(uint4*)&kv[i];
                *(uint4*)&Vs[r * 72 + c4 * 4] = *(uint4*)&vv[i];
            }
        }
    }

    if (t == 0) {
        g_mbuf[row_g + wq + g] = m0r;
        g_lbuf[row_g + wq + g] = l0r;
        g_mbuf[row_g + wq + g + 8] = m1r;
        g_lbuf[row_g + wq + g + 8] = l1r;
    }

    // Context epilogue: out = acc / l, RN-rounded to tf32 (feeds out projection)
    const float il0 = 1.0f / l0r, il1 = 1.0f / l1r;
#pragma unroll
    for (int nf = 0; nf < 8; nf++) {
        int col = nf * 8 + 2 * t;
        *(float2*)&g_ctx[((size_t)b * Sc + q0 + wq + g) * Dc + h * HDc + col] =
            make_float2(frnd(acc[nf][0] * il0), frnd(acc[nf][1] * il0));
        *(float2*)&g_ctx[((size_t)b * Sc + q0 + wq + g + 8) * Dc + h * HDc + col] =
            make_float2(frnd(acc[nf][2] * il1), frnd(acc[nf][3] * il1));
    }
}

// ---------------------------------------------------------------------------
extern "C" void kernel_launch(void* const* d_in, const int* in_sizes, int n_in,
                              void* d_out, int out_size) {
    const float* query = (const float*)d_in[0];
    const float* key_  = (const float*)d_in[1];
    const float* value = (const float*)d_in[2];
    const float* Wq = (const float*)d_in[3];
    const float* bq = (const float*)d_in[4];
    const float* Wk = (const float*)d_in[5];
    const float* bk = (const float*)d_in[6];
    const float* Wv = (const float*)d_in[7];
    const float* bv = (const float*)d_in[8];
    const float* Wo = (const float*)d_in[9];
    const float* bo = (const float*)d_in[10];
    float* out = (float*)d_out;

    const size_t OUT_ELEMS = (size_t)Bc * Sc * Dc;            // 4,194,304
    float* attn_ptr;
    if ((size_t)out_size >= OUT_ELEMS + ATTN_ELEMS_C) {
        attn_ptr = out + OUT_ELEMS;
    } else {
        cudaGetSymbolAddress((void**)&attn_ptr, g_attn_scratch);
    }

    cudaFuncSetAttribute(attn_flash,
                         cudaFuncAttributeMaxDynamicSharedMemorySize,
                         ATTN_SMEM_BYTES);
    cudaFuncSetAttribute(qkv_gemm,
                         cudaFuncAttributeMaxDynamicSharedMemorySize,
                         GEMM_SMEM_BYTES);
    cudaFuncSetAttribute(fused_tail,
                         cudaFuncAttributeMaxDynamicSharedMemorySize,
                         TAIL_SMEM_BYTES);

    // RN-round inputs + weights to tf32 (makes all cp.async truncation exact)
    pre_round<<<dim3(4096, 7), 256>>>(query, key_, value, Wq, Wk, Wv, Wo);

    // Fused Q/K/V projections (outputs RN-rounded to tf32)
    qkv_gemm<<<dim3(BSc / 128, Dc / 128, 3), 256, GEMM_SMEM_BYTES>>>(bq, bk, bv);

    attn_flash<<<dim3(Sc / 128, Hc, Bc), 256, ATTN_SMEM_BYTES>>>(attn_ptr);

    // Tail: normalize (z=0..7, first) co-scheduled with out-projection (z=8..11)
    fused_tail<<<dim3(32, 8, 12), 256, TAIL_SMEM_BYTES>>>(bo, out, attn_ptr);
}